// round 14
// baseline (speedup 1.0000x reference)
#include <cuda_runtime.h>
#include <cuda_fp16.h>
#include <cuda_bf16.h>
#include <mma.h>
#include <cuda_pipeline.h>
#include <cstdint>

using namespace nvcuda;

// ---------------------------------------------------------------------------
// out[M,N] = x[M,K] @ dequant(qweight,qzeros,scales)[K,N] + bias[N]
//   M=8192, K=4096, N=4096, GPTQ 4-bit, groupsize 128.
// R14: R13 anti-convoy mainloop, register-budgeted to fit 128 regs:
//   - af[2][2] double-buffered across ks (32 regs)
//   - bf[2] ROLLING buffer across j (16 regs): LDSM for j+1 / next-ks j=0
//     issued before the 2 MMAs of column j -> every LDSM covered, no seams
//   - acc 64 + frags 48 + addressing ~14 = ~126 regs (R13 demanded ~160 and
//     spilled at the 128 cap, nullifying half the overlap)
// Shape held fixed: BK=64, NSTAGE=3, 128x128 CTA tile, 8 warps, 32x64/warp,
// 2 CTAs/SM. tcgen05 unreachable (harness ptxas target sm_103).
// ---------------------------------------------------------------------------

#define BM 128
#define BN 128
#define BK 64
#define LDA 72    // BK + 8 halves padding
#define LDB 136   // BN + 8 halves padding
#define NSTAGE 3
#define KSTEPS (BK / 16)   // 4 (even: bf parity is seamless across ks)

#define A_ST (BM * LDA)                      // 9216 halves / stage
#define B_ST (BK * LDB)                      // 8704 halves / stage
#define SMEM_BYTES (NSTAGE * (A_ST + B_ST) * 2)   // 107520 B -> 2 CTAs/SM

__device__ __half g_W[4096u * 4096u];        // dequantized W [K,N], 32 MB
__device__ __half g_X[8192u * 4096u];        // x as fp16, 64 MB
__device__ int    g_dtype;                   // 0=fp16, 1=fp32, 2=bf16

#define PROBE_WORDS 16384

// ============================ dtype probe ==================================
__global__ void probe_kernel(const uint32_t* __restrict__ x) {
    __shared__ int sh[5];
    int tid = threadIdx.x;
    if (tid < 5) sh[tid] = 0;
    __syncthreads();
    int f16s = 0, f16m = 0, w32s = 0, w32m = 0, lob = 0;
    for (int i = tid; i < PROBE_WORDS; i += 256) {
        uint32_t w = x[i];
#pragma unroll
        for (int h = 0; h < 2; h++) {
            __half_raw hr; hr.x = (uint16_t)(w >> (16 * h));
            float v = fabsf(__half2float((__half)hr));
            if (v > 1e-4f && v < 64.f) f16s++;
            if (v > 0.01f && v < 0.5f) f16m++;
        }
        float f = fabsf(__uint_as_float(w));
        if (f > 1e-4f && f < 64.f) w32s++;
        if (f > 0.01f && f < 0.5f) w32m++;
        float lb = fabsf(__uint_as_float((w & 0xFFFFu) << 16));
        if (lb > 1e-4f && lb < 64.f) lob++;
    }
    atomicAdd(&sh[0], f16s); atomicAdd(&sh[1], f16m);
    atomicAdd(&sh[2], w32s); atomicAdd(&sh[3], w32m);
    atomicAdd(&sh[4], lob);
    __syncthreads();
    if (tid == 0) {
        const int n = PROBE_WORDS;
        bool fp16_ok = sh[0] > (int)(0.95f * 2 * n) &&
                       sh[1] > (int)(0.20f * 2 * n) && sh[1] < (int)(0.55f * 2 * n);
        bool w32_ok  = sh[2] > (int)(0.95f * n) &&
                       sh[3] > (int)(0.20f * n) && sh[3] < (int)(0.55f * n);
        int dt;
        if (fp16_ok)     dt = 0;
        else if (w32_ok) dt = (sh[4] > (int)(0.90f * n)) ? 2 : 1;
        else             dt = 1;
        g_dtype = dt;
    }
}

__device__ __forceinline__ float load_scalar_f(const void* p, size_t idx, int dt) {
    if (dt == 1) return ((const float*)p)[idx];
    if (dt == 2) return __uint_as_float((uint32_t)((const uint16_t*)p)[idx] << 16);
    __half_raw hr; hr.x = ((const uint16_t*)p)[idx];
    return __half2float((__half)hr);
}

// ======================= convert x -> fp16 (g_X) ===========================
__global__ void convert_x_kernel(const void* __restrict__ x, size_t n8) {
    int dt = g_dtype;
    if (dt == 0) return;
    size_t i = (size_t)blockIdx.x * blockDim.x + threadIdx.x;
    if (i >= n8) return;
    __half out[8];
    if (dt == 1) {
        const float4* p = (const float4*)x + i * 2;
        float4 a = p[0], b = p[1];
        out[0] = __float2half(a.x); out[1] = __float2half(a.y);
        out[2] = __float2half(a.z); out[3] = __float2half(a.w);
        out[4] = __float2half(b.x); out[5] = __float2half(b.y);
        out[6] = __float2half(b.z); out[7] = __float2half(b.w);
    } else {
        uint4 v = ((const uint4*)x)[i];
        uint32_t ws[4] = {v.x, v.y, v.z, v.w};
#pragma unroll
        for (int j = 0; j < 4; j++) {
            out[2*j]   = __float2half(__uint_as_float((ws[j] & 0xFFFFu) << 16));
            out[2*j+1] = __float2half(__uint_as_float(ws[j] & 0xFFFF0000u));
        }
    }
    ((uint4*)g_X)[i] = *(const uint4*)out;
}

// ============ dequant -> g_W[k][n] (row-major, wmma B operand) =============
__global__ void dequant_kernel(const uint32_t* __restrict__ qweight,
                               const uint32_t* __restrict__ qzeros,
                               const void* __restrict__ scales,
                               int K, int N) {
    int dt = g_dtype;
    int tid = blockIdx.x * blockDim.x + threadIdx.x;
    int oOct = N >> 3;
    int kOct = K >> 3;
    int ob = tid % oOct;
    int kb = tid / oOct;
    if (kb >= kOct) return;

    int o0 = ob << 3;
    int k0 = kb << 3;
    int g  = k0 >> 7;   // groupsize 128

    uint32_t qw[8];
    const uint32_t* qrow = qweight + (size_t)kb * N + o0;
#pragma unroll
    for (int i = 0; i < 8; i++) qw[i] = qrow[i];

    uint32_t zword = qzeros[(size_t)g * oOct + ob];

    float zf[8], sf[8];
#pragma unroll
    for (int i = 0; i < 8; i++) {
        zf[i] = (float)(((zword >> (4 * i)) & 15u) + 1u);
        sf[i] = load_scalar_f(scales, (size_t)g * N + o0 + i, dt);
    }
#pragma unroll
    for (int j = 0; j < 8; j++) {    // k = k0+j uses nibble j
        __half vals[8];
#pragma unroll
        for (int i = 0; i < 8; i++) {
            float w = (float)((qw[i] >> (4 * j)) & 15u);
            // exact fp32 product, single RN round to fp16 == reference
            vals[i] = __float2half((w - zf[i]) * sf[i]);
        }
        *(uint4*)(&g_W[(size_t)(k0 + j) * N + o0]) = *(const uint4*)vals;
    }
}

// ============================ HMMA GEMM ====================================
// 128x128x64 tile, 8 warps (4 x 2), 32x64 per warp, 3-stage cp.async,
// af ks-double-buffer + bf rolling prefetch. 2 CTAs/SM enforced.
__global__ void __launch_bounds__(256, 2)
gemm_kernel(const void* __restrict__ x_in,
            const void* __restrict__ bias,
            void* __restrict__ C,
            int M, int N, int K) {
    extern __shared__ char dsm[];
    __half* sA = (__half*)dsm;                          // NSTAGE * A_ST
    __half* sB = (__half*)(dsm + NSTAGE * A_ST * 2);    // NSTAGE * B_ST
    float*  sStage = (float*)dsm;  // epilogue staging ALIASES pipeline smem
                                   // (dead after final __syncthreads)

    const int dt    = g_dtype;
    const int tid   = threadIdx.x;
    const int warp  = tid >> 5;
    const int lane  = tid & 31;
    const int m0    = blockIdx.y * BM;
    const int n0    = blockIdx.x * BN;
    const int warp_m = warp & 3;   // 4 warps along M, 32 rows each
    const int warp_n = warp >> 2;  // 2 warps along N, 64 cols each

    const __half* __restrict__ A = (dt == 0) ? (const __half*)x_in : g_X;
    const __half* __restrict__ B = g_W;

    wmma::fragment<wmma::accumulator, 16, 16, 16, float> acc[2][4];
#pragma unroll
    for (int i = 0; i < 2; i++)
#pragma unroll
        for (int j = 0; j < 4; j++) wmma::fill_fragment(acc[i][j], 0.0f);

    const int NT = K / BK;   // 64

    auto load_tiles = [&](int chunk) {
        const int s  = chunk % NSTAGE;
        const int k0 = chunk * BK;
        __half* aS = sA + s * A_ST;
        __half* bS = sB + s * B_ST;
        // A: 128 rows x 8 x 16B segs = 1024 segs, 4/thread
#pragma unroll
        for (int r = 0; r < 4; r++) {
            int t = tid + r * 256;
            int row = t >> 3;
            int seg = t & 7;
            __pipeline_memcpy_async(aS + row * LDA + seg * 8,
                                    A + ((size_t)(m0 + row) * K + k0 + seg * 8), 16);
        }
        // B: 64 rows x 16 x 16B segs = 1024 segs, 4/thread
#pragma unroll
        for (int r = 0; r < 4; r++) {
            int t = tid + r * 256;
            int row = t >> 4;
            int seg = t & 15;
            __pipeline_memcpy_async(bS + row * LDB + seg * 8,
                                    B + ((size_t)(k0 + row) * N + n0 + seg * 8), 16);
        }
    };

    // Prologue: stages 0..1
#pragma unroll
    for (int c = 0; c < NSTAGE - 1; c++) {
        load_tiles(c);
        __pipeline_commit();
    }

    wmma::fragment<wmma::matrix_a, 16, 16, 16, __half, wmma::row_major> af[2][2];
    wmma::fragment<wmma::matrix_b, 16, 16, 16, __half, wmma::row_major> bf[2];

    for (int kt = 0; kt < NT; ++kt) {
        __pipeline_wait_prior(NSTAGE - 2);   // stage kt resident
        __syncthreads();                     // all warps done with stage kt-1
        if (kt + NSTAGE - 1 < NT)
            load_tiles(kt + NSTAGE - 1);     // overwrites stage (kt-1)%NSTAGE
        __pipeline_commit();

        const int s = kt % NSTAGE;
        const __half* aS = sA + s * A_ST + (warp_m * 32) * LDA;
        const __half* bS = sB + s * B_ST + warp_n * 64;

        // Preload: A frags for ks=0, first B frag (ks=0, j=0)
#pragma unroll
        for (int i = 0; i < 2; i++)
            wmma::load_matrix_sync(af[0][i], aS + (i * 16) * LDA, LDA);
        wmma::load_matrix_sync(bf[0], bS, LDB);

#pragma unroll
        for (int ks = 0; ks < KSTEPS; ks++) {
            const int cur = ks & 1;
            if (ks + 1 < KSTEPS) {
                // A frags for ks+1: covered by the 8 MMAs of this ks
#pragma unroll
                for (int i = 0; i < 2; i++)
                    wmma::load_matrix_sync(af[cur ^ 1][i],
                        aS + (i * 16) * LDA + (ks + 1) * 16, LDA);
            }
#pragma unroll
            for (int j = 0; j < 4; j++) {
                const int bc = j & 1;
                // rolling prefetch: next column's B frag issued before the
                // 2 MMAs of column j (seam to next ks included; KSTEPS even
                // keeps the parity consistent: last store -> bf[0], next ks
                // starts reading bf[0])
                if (j + 1 < 4)
                    wmma::load_matrix_sync(bf[bc ^ 1],
                        bS + (ks * 16) * LDB + (j + 1) * 16, LDB);
                else if (ks + 1 < KSTEPS)
                    wmma::load_matrix_sync(bf[bc ^ 1],
                        bS + ((ks + 1) * 16) * LDB, LDB);
#pragma unroll
                for (int i = 0; i < 2; i++)
                    wmma::mma_sync(acc[i][j], af[cur][i], bf[bc], acc[i][j]);
            }
        }
    }
    __syncthreads();   // pipeline smem now dead; sStage alias becomes live

    // Epilogue: fp32 -> fp16 round -> fp16 bias add -> store in detected dtype
    float* myStage = sStage + warp * 16 * 20;
#pragma unroll
    for (int i = 0; i < 2; i++) {
#pragma unroll
        for (int j = 0; j < 4; j++) {
            wmma::store_matrix_sync(myStage, acc[i][j], 20, wmma::mem_row_major);
            __syncwarp();
            const int row  = lane >> 1;
            const int col0 = (lane & 1) * 8;
            const int gm  = m0 + warp_m * 32 + i * 16 + row;
            const int gn0 = n0 + warp_n * 64 + j * 16 + col0;
            __half h[8];
#pragma unroll
            for (int e = 0; e < 8; e++) {
                __half hv = __float2half(myStage[row * 20 + col0 + e]);
                __half bh = __float2half(load_scalar_f(bias, gn0 + e, dt));
                h[e] = __hadd(hv, bh);
            }
            size_t off = (size_t)gm * N + gn0;
            if (dt == 1) {
                float fo[8];
#pragma unroll
                for (int e = 0; e < 8; e++) fo[e] = __half2float(h[e]);
                float4* po = (float4*)((float*)C + off);
                po[0] = *(const float4*)&fo[0];
                po[1] = *(const float4*)&fo[4];
            } else if (dt == 2) {
                uint16_t bo[8];
#pragma unroll
                for (int e = 0; e < 8; e++) {
                    __nv_bfloat16 b = __float2bfloat16(__half2float(h[e]));
                    bo[e] = *(const uint16_t*)&b;
                }
                *(uint4*)((uint16_t*)C + off) = *(const uint4*)bo;
            } else {
                *(uint4*)((__half*)C + off) = *(const uint4*)h;
            }
            __syncwarp();
        }
    }
}

// ================================ launch ===================================
extern "C" void kernel_launch(void* const* d_in, const int* in_sizes, int n_in,
                              void* d_out, int out_size) {
    int idx[5] = {0, 1, 2, 3, 4};
    for (int a = 0; a < 5; a++)
        for (int b = a + 1; b < 5; b++)
            if (in_sizes[idx[b]] > in_sizes[idx[a]]) { int t = idx[a]; idx[a] = idx[b]; idx[b] = t; }

    const void*     x       = d_in[idx[0]];                  // largest: x
    const uint32_t* qweight = (const uint32_t*)d_in[idx[1]];
    const void*     scales  = d_in[idx[2]];
    const uint32_t* qzeros  = (const uint32_t*)d_in[idx[3]];
    const void*     bias    = d_in[idx[4]];

    const int N = in_sizes[idx[4]];                              // 4096
    const int K = (int)(((long long)in_sizes[idx[1]] * 8) / N);  // 4096
    const int M = (int)((long long)in_sizes[idx[0]] / K);        // 8192

    probe_kernel<<<1, 256>>>((const uint32_t*)x);

    {
        size_t n8 = (size_t)M * K / 8;
        int threads = 256;
        int blocks = (int)((n8 + threads - 1) / threads);
        convert_x_kernel<<<blocks, threads>>>(x, n8);
    }
    {
        int total = (K >> 3) * (N >> 3);
        int threads = 256;
        int blocks = (total + threads - 1) / threads;
        dequant_kernel<<<blocks, threads>>>(qweight, qzeros, scales, K, N);
    }
    {
        cudaFuncSetAttribute(gemm_kernel,
                             cudaFuncAttributeMaxDynamicSharedMemorySize,
                             SMEM_BYTES);
        dim3 grid(N / BN, M / BM);   // (32, 64)
        gemm_kernel<<<grid, 256, SMEM_BYTES>>>(x, bias, d_out, M, N, K);
    }
}

// round 16
// speedup vs baseline: 1.1722x; 1.1722x over previous
#include <cuda_runtime.h>
#include <cuda_fp16.h>
#include <cuda_bf16.h>
#include <mma.h>
#include <cuda_pipeline.h>
#include <cstdint>

using namespace nvcuda;

// ---------------------------------------------------------------------------
// out[M,N] = x[M,K] @ dequant(qweight,qzeros,scales)[K,N] + bias[N]
//   M=8192, K=4096, N=4096, GPTQ 4-bit, groupsize 128.
// R16 == R15 resubmit (R15 hit an infra failure before execution).
// R15: issue-slot reclamation. R13/R14 profile: ALU 13.7% + FMA(IMAD) 7.1%
//      of issue is cp.async addressing; LDGSTS bursts clump at loop head.
//   - all load addressing hoisted: rolling global pointers (+BK / +BK*N per
//     chunk), precomputed smem offsets; ~40 fewer integer instr per chunk
//   - 8 cp.async issues spread 2-per-ks across the 4 ks steps (A: ks0/1,
//     B: ks2/3), commit once per chunk (group accounting == R13, audited)
//   - fragment structure (af ks-double-buffer + bf rolling), BK=64, NSTAGE=3,
//     128x128 tile, 8 warps, 32x64/warp, 2 CTAs/SM: all unchanged
// tcgen05 unreachable (harness ptxas target sm_103).
// ---------------------------------------------------------------------------

#define BM 128
#define BN 128
#define BK 64
#define LDA 72    // BK + 8 halves padding
#define LDB 136   // BN + 8 halves padding
#define NSTAGE 3
#define KSTEPS (BK / 16)   // 4

#define A_ST (BM * LDA)                      // 9216 halves / stage
#define B_ST (BK * LDB)                      // 8704 halves / stage
#define SMEM_BYTES (NSTAGE * (A_ST + B_ST) * 2)   // 107520 B -> 2 CTAs/SM

__device__ __half g_W[4096u * 4096u];        // dequantized W [K,N], 32 MB
__device__ __half g_X[8192u * 4096u];        // x as fp16, 64 MB
__device__ int    g_dtype;                   // 0=fp16, 1=fp32, 2=bf16

#define PROBE_WORDS 16384

// ============================ dtype probe ==================================
__global__ void probe_kernel(const uint32_t* __restrict__ x) {
    __shared__ int sh[5];
    int tid = threadIdx.x;
    if (tid < 5) sh[tid] = 0;
    __syncthreads();
    int f16s = 0, f16m = 0, w32s = 0, w32m = 0, lob = 0;
    for (int i = tid; i < PROBE_WORDS; i += 256) {
        uint32_t w = x[i];
#pragma unroll
        for (int h = 0; h < 2; h++) {
            __half_raw hr; hr.x = (uint16_t)(w >> (16 * h));
            float v = fabsf(__half2float((__half)hr));
            if (v > 1e-4f && v < 64.f) f16s++;
            if (v > 0.01f && v < 0.5f) f16m++;
        }
        float f = fabsf(__uint_as_float(w));
        if (f > 1e-4f && f < 64.f) w32s++;
        if (f > 0.01f && f < 0.5f) w32m++;
        float lb = fabsf(__uint_as_float((w & 0xFFFFu) << 16));
        if (lb > 1e-4f && lb < 64.f) lob++;
    }
    atomicAdd(&sh[0], f16s); atomicAdd(&sh[1], f16m);
    atomicAdd(&sh[2], w32s); atomicAdd(&sh[3], w32m);
    atomicAdd(&sh[4], lob);
    __syncthreads();
    if (tid == 0) {
        const int n = PROBE_WORDS;
        bool fp16_ok = sh[0] > (int)(0.95f * 2 * n) &&
                       sh[1] > (int)(0.20f * 2 * n) && sh[1] < (int)(0.55f * 2 * n);
        bool w32_ok  = sh[2] > (int)(0.95f * n) &&
                       sh[3] > (int)(0.20f * n) && sh[3] < (int)(0.55f * n);
        int dt;
        if (fp16_ok)     dt = 0;
        else if (w32_ok) dt = (sh[4] > (int)(0.90f * n)) ? 2 : 1;
        else             dt = 1;
        g_dtype = dt;
    }
}

__device__ __forceinline__ float load_scalar_f(const void* p, size_t idx, int dt) {
    if (dt == 1) return ((const float*)p)[idx];
    if (dt == 2) return __uint_as_float((uint32_t)((const uint16_t*)p)[idx] << 16);
    __half_raw hr; hr.x = ((const uint16_t*)p)[idx];
    return __half2float((__half)hr);
}

// ======================= convert x -> fp16 (g_X) ===========================
__global__ void convert_x_kernel(const void* __restrict__ x, size_t n8) {
    int dt = g_dtype;
    if (dt == 0) return;
    size_t i = (size_t)blockIdx.x * blockDim.x + threadIdx.x;
    if (i >= n8) return;
    __half out[8];
    if (dt == 1) {
        const float4* p = (const float4*)x + i * 2;
        float4 a = p[0], b = p[1];
        out[0] = __float2half(a.x); out[1] = __float2half(a.y);
        out[2] = __float2half(a.z); out[3] = __float2half(a.w);
        out[4] = __float2half(b.x); out[5] = __float2half(b.y);
        out[6] = __float2half(b.z); out[7] = __float2half(b.w);
    } else {
        uint4 v = ((const uint4*)x)[i];
        uint32_t ws[4] = {v.x, v.y, v.z, v.w};
#pragma unroll
        for (int j = 0; j < 4; j++) {
            out[2*j]   = __float2half(__uint_as_float((ws[j] & 0xFFFFu) << 16));
            out[2*j+1] = __float2half(__uint_as_float(ws[j] & 0xFFFF0000u));
        }
    }
    ((uint4*)g_X)[i] = *(const uint4*)out;
}

// ============ dequant -> g_W[k][n] (row-major, wmma B operand) =============
__global__ void dequant_kernel(const uint32_t* __restrict__ qweight,
                               const uint32_t* __restrict__ qzeros,
                               const void* __restrict__ scales,
                               int K, int N) {
    int dt = g_dtype;
    int tid = blockIdx.x * blockDim.x + threadIdx.x;
    int oOct = N >> 3;
    int kOct = K >> 3;
    int ob = tid % oOct;
    int kb = tid / oOct;
    if (kb >= kOct) return;

    int o0 = ob << 3;
    int k0 = kb << 3;
    int g  = k0 >> 7;   // groupsize 128

    uint32_t qw[8];
    const uint32_t* qrow = qweight + (size_t)kb * N + o0;
#pragma unroll
    for (int i = 0; i < 8; i++) qw[i] = qrow[i];

    uint32_t zword = qzeros[(size_t)g * oOct + ob];

    float zf[8], sf[8];
#pragma unroll
    for (int i = 0; i < 8; i++) {
        zf[i] = (float)(((zword >> (4 * i)) & 15u) + 1u);
        sf[i] = load_scalar_f(scales, (size_t)g * N + o0 + i, dt);
    }
#pragma unroll
    for (int j = 0; j < 8; j++) {    // k = k0+j uses nibble j
        __half vals[8];
#pragma unroll
        for (int i = 0; i < 8; i++) {
            float w = (float)((qw[i] >> (4 * j)) & 15u);
            // exact fp32 product, single RN round to fp16 == reference
            vals[i] = __float2half((w - zf[i]) * sf[i]);
        }
        *(uint4*)(&g_W[(size_t)(k0 + j) * N + o0]) = *(const uint4*)vals;
    }
}

// ============================ HMMA GEMM ====================================
// 128x128x64 tile, 8 warps (4 x 2), 32x64 per warp, 3-stage cp.async with
// hoisted addressing + per-ks spread issue. 2 CTAs/SM enforced.
__global__ void __launch_bounds__(256, 2)
gemm_kernel(const void* __restrict__ x_in,
            const void* __restrict__ bias,
            void* __restrict__ C,
            int M, int N, int K) {
    extern __shared__ char dsm[];
    __half* sA = (__half*)dsm;                          // NSTAGE * A_ST
    __half* sB = (__half*)(dsm + NSTAGE * A_ST * 2);    // NSTAGE * B_ST
    float*  sStage = (float*)dsm;  // epilogue staging ALIASES pipeline smem

    const int dt    = g_dtype;
    const int tid   = threadIdx.x;
    const int warp  = tid >> 5;
    const int lane  = tid & 31;
    const int m0    = blockIdx.y * BM;
    const int n0    = blockIdx.x * BN;
    const int warp_m = warp & 3;   // 4 warps along M, 32 rows each
    const int warp_n = warp >> 2;  // 2 warps along N, 64 cols each

    const __half* __restrict__ A = (dt == 0) ? (const __half*)x_in : g_X;
    const __half* __restrict__ B = g_W;

    // ---- hoisted per-thread load addressing ----
    const int aRow = tid >> 3, aSeg = tid & 7;     // A: 32 rows/phase, 8 segs
    const int bRow = tid >> 4, bSeg = tid & 15;    // B: 16 rows/phase, 16 segs
    const __half* aGp = A + (size_t)(m0 + aRow) * K + aSeg * 8;  // chunk 0
    const __half* bGp = B + (size_t)bRow * N + n0 + bSeg * 8;
    const size_t stepAr = (size_t)32 * K;          // +32 rows
    const size_t stepBr = (size_t)16 * N;          // +16 rows
    const size_t advB   = (size_t)BK * N;          // per-chunk B advance
    const uint32_t aOff0 = aRow * LDA + aSeg * 8;  // smem offsets (halves)
    const uint32_t bOff0 = bRow * LDB + bSeg * 8;

    wmma::fragment<wmma::accumulator, 16, 16, 16, float> acc[2][4];
#pragma unroll
    for (int i = 0; i < 2; i++)
#pragma unroll
        for (int j = 0; j < 4; j++) wmma::fill_fragment(acc[i][j], 0.0f);

    const int NT = K / BK;   // 64

    // Prologue: chunks 0,1 -> stages 0,1
#pragma unroll
    for (int c = 0; c < NSTAGE - 1; c++) {
        __half* aLd = sA + c * A_ST;
        __half* bLd = sB + c * B_ST;
#pragma unroll
        for (int r = 0; r < 4; r++)
            __pipeline_memcpy_async(aLd + aOff0 + r * (32 * LDA),
                                    aGp + r * stepAr, 16);
#pragma unroll
        for (int r = 0; r < 4; r++)
            __pipeline_memcpy_async(bLd + bOff0 + r * (16 * LDB),
                                    bGp + r * stepBr, 16);
        __pipeline_commit();
        aGp += BK;
        bGp += advB;
    }

    wmma::fragment<wmma::matrix_a, 16, 16, 16, __half, wmma::row_major> af[2][2];
    wmma::fragment<wmma::matrix_b, 16, 16, 16, __half, wmma::row_major> bf[2];

    int ls = 2;   // stage receiving the next load (chunk kt+2)
    for (int kt = 0; kt < NT; ++kt) {
        __pipeline_wait_prior(NSTAGE - 2);   // chunk kt resident
        __syncthreads();                     // all warps done with stage kt-1
        const bool doLoad = (kt + NSTAGE - 1) < NT;
        __half* aLd = sA + ls * A_ST;
        __half* bLd = sB + ls * B_ST;

        const int s = kt % NSTAGE;
        const __half* aS = sA + s * A_ST + (warp_m * 32) * LDA;
        const __half* bS = sB + s * B_ST + warp_n * 64;

        // Preload: A frags for ks=0, first B frag
#pragma unroll
        for (int i = 0; i < 2; i++)
            wmma::load_matrix_sync(af[0][i], aS + (i * 16) * LDA, LDA);
        wmma::load_matrix_sync(bf[0], bS, LDB);

#pragma unroll
        for (int ks = 0; ks < KSTEPS; ks++) {
            const int cur = ks & 1;
            // spread cp.async: 2 ops per ks (A in ks0/1, B in ks2/3)
            if (doLoad) {
                if (ks < 2) {
#pragma unroll
                    for (int r = 0; r < 2; r++) {
                        const int rr = ks * 2 + r;
                        __pipeline_memcpy_async(aLd + aOff0 + rr * (32 * LDA),
                                                aGp + rr * stepAr, 16);
                    }
                } else {
#pragma unroll
                    for (int r = 0; r < 2; r++) {
                        const int rr = (ks - 2) * 2 + r;
                        __pipeline_memcpy_async(bLd + bOff0 + rr * (16 * LDB),
                                                bGp + rr * stepBr, 16);
                    }
                }
            }
            if (ks + 1 < KSTEPS) {
#pragma unroll
                for (int i = 0; i < 2; i++)
                    wmma::load_matrix_sync(af[cur ^ 1][i],
                        aS + (i * 16) * LDA + (ks + 1) * 16, LDA);
            }
#pragma unroll
            for (int j = 0; j < 4; j++) {
                const int bc = j & 1;
                if (j + 1 < 4)
                    wmma::load_matrix_sync(bf[bc ^ 1],
                        bS + (ks * 16) * LDB + (j + 1) * 16, LDB);
                else if (ks + 1 < KSTEPS)
                    wmma::load_matrix_sync(bf[bc ^ 1],
                        bS + ((ks + 1) * 16) * LDB, LDB);
#pragma unroll
                for (int i = 0; i < 2; i++)
                    wmma::mma_sync(acc[i][j], af[cur][i], bf[bc], acc[i][j]);
            }
        }

        __pipeline_commit();                 // one group per chunk (may be empty)
        if (doLoad) { aGp += BK; bGp += advB; }
        if (++ls == NSTAGE) ls = 0;
    }
    __syncthreads();   // pipeline smem now dead; sStage alias becomes live

    // Epilogue: fp32 -> fp16 round -> fp16 bias add -> store in detected dtype
    float* myStage = sStage + warp * 16 * 20;
#pragma unroll
    for (int i = 0; i < 2; i++) {
#pragma unroll
        for (int j = 0; j < 4; j++) {
            wmma::store_matrix_sync(myStage, acc[i][j], 20, wmma::mem_row_major);
            __syncwarp();
            const int row  = lane >> 1;
            const int col0 = (lane & 1) * 8;
            const int gm  = m0 + warp_m * 32 + i * 16 + row;
            const int gn0 = n0 + warp_n * 64 + j * 16 + col0;
            __half h[8];
#pragma unroll
            for (int e = 0; e < 8; e++) {
                __half hv = __float2half(myStage[row * 20 + col0 + e]);
                __half bh = __float2half(load_scalar_f(bias, gn0 + e, dt));
                h[e] = __hadd(hv, bh);
            }
            size_t off = (size_t)gm * N + gn0;
            if (dt == 1) {
                float fo[8];
#pragma unroll
                for (int e = 0; e < 8; e++) fo[e] = __half2float(h[e]);
                float4* po = (float4*)((float*)C + off);
                po[0] = *(const float4*)&fo[0];
                po[1] = *(const float4*)&fo[4];
            } else if (dt == 2) {
                uint16_t bo[8];
#pragma unroll
                for (int e = 0; e < 8; e++) {
                    __nv_bfloat16 b = __float2bfloat16(__half2float(h[e]));
                    bo[e] = *(const uint16_t*)&b;
                }
                *(uint4*)((uint16_t*)C + off) = *(const uint4*)bo;
            } else {
                *(uint4*)((__half*)C + off) = *(const uint4*)h;
            }
            __syncwarp();
        }
    }
}

// ================================ launch ===================================
extern "C" void kernel_launch(void* const* d_in, const int* in_sizes, int n_in,
                              void* d_out, int out_size) {
    int idx[5] = {0, 1, 2, 3, 4};
    for (int a = 0; a < 5; a++)
        for (int b = a + 1; b < 5; b++)
            if (in_sizes[idx[b]] > in_sizes[idx[a]]) { int t = idx[a]; idx[a] = idx[b]; idx[b] = t; }

    const void*     x       = d_in[idx[0]];                  // largest: x
    const uint32_t* qweight = (const uint32_t*)d_in[idx[1]];
    const void*     scales  = d_in[idx[2]];
    const uint32_t* qzeros  = (const uint32_t*)d_in[idx[3]];
    const void*     bias    = d_in[idx[4]];

    const int N = in_sizes[idx[4]];                              // 4096
    const int K = (int)(((long long)in_sizes[idx[1]] * 8) / N);  // 4096
    const int M = (int)((long long)in_sizes[idx[0]] / K);        // 8192

    probe_kernel<<<1, 256>>>((const uint32_t*)x);

    {
        size_t n8 = (size_t)M * K / 8;
        int threads = 256;
        int blocks = (int)((n8 + threads - 1) / threads);
        convert_x_kernel<<<blocks, threads>>>(x, n8);
    }
    {
        int total = (K >> 3) * (N >> 3);
        int threads = 256;
        int blocks = (total + threads - 1) / threads;
        dequant_kernel<<<blocks, threads>>>(qweight, qzeros, scales, K, N);
    }
    {
        cudaFuncSetAttribute(gemm_kernel,
                             cudaFuncAttributeMaxDynamicSharedMemorySize,
                             SMEM_BYTES);
        dim3 grid(N / BN, M / BM);   // (32, 64)
        gemm_kernel<<<grid, 256, SMEM_BYTES>>>(x, bias, d_out, M, N, K);
    }
}